// round 6
// baseline (speedup 1.0000x reference)
#include <cuda_runtime.h>
#include <cuda_bf16.h>

// WaveletTransform: 3-level low-pass pyramid on x[8,32,512,512] fp32.
// out = x, except per-channel:
//   out[0:256,0:256] = down2x(conv3x3(x[0:512,0:512]))        (level 0)
//   out[0:128,0:128] = down2x(conv3x3(level0 result[0:256]^2)) (level 1)
//   out[0: 64,0: 64] = down2x(conv3x3(level1 result[0:128]^2)) (level 2)
// conv = outer([.25,.5,.25],[.25,.5,.25]), zero-padded 'same', even-index
// downsample (center 2i,2j -> taps 2i-1..2i+1).
//
// R6: ONE kernel, one CTA per channel (256 CTAs x 1024 thr, 68KB smem).
//   Phase A: level-0 conv quadrant + float4 copy of the rest (as R3 K1).
//   Phase B: level-1 conv reading back the quadrant this CTA just wrote
//            (L2-hot -> removes K23's DRAM reads) into smem.
//   Phase C: level-2 conv (inner 64^2) + writeback of 128^2 region.
// R5's stream fork-join regressed (DRAM-bound: overlap can't beat
// traffic/BW) and is reverted.

#define BC_TOTAL (8 * 32)
#define H0 512
#define W0C 512

#define L1_STRIDE 132                       // 128 + 4 floats pad
#define SMEM_BYTES (128 * L1_STRIDE * 4)    // 67584

__device__ __forceinline__ float hfilt(float a, float b, float c) {
    return 0.25f * a + 0.5f * b + 0.25f * c;
}

__global__ void __launch_bounds__(1024) wavelet_all(
    const float* __restrict__ x, float* __restrict__ out)
{
    extern __shared__ float l1[];               // [128][L1_STRIDE]
    const int tid = threadIdx.x;
    const int bc  = blockIdx.x;

    const float* xp = x   + (size_t)bc * H0 * W0C;
    float*       op = out + (size_t)bc * H0 * W0C;

    // ---- Phase A1: level-0 conv-down -> out[0:256, 0:256] ----
    // j4 = output float4 col (0..63), rg picks 16 rows. Warp halves have
    // uniform i, so the r<0 skip is warp-uniform.
    {
        const int j4 = tid & 63;                 // 0..63
        const int rg = tid >> 6;                 // 0..15
        #pragma unroll 4
        for (int it = 0; it < 16; it++) {
            const int i  = rg * 16 + it;         // 0..255
            const int r0 = 2 * i - 1;            // -1 only when i==0
            float acc0 = 0.f, acc1 = 0.f, acc2 = 0.f, acc3 = 0.f;
            #pragma unroll
            for (int a = 0; a < 3; a++) {
                const int r = r0 + a;            // <= 511
                if (r < 0) continue;             // warp-uniform
                const float wr = (a == 1) ? 0.5f : 0.25f;
                const float* row = xp + (size_t)r * W0C;
                const float4* rv = reinterpret_cast<const float4*>(row) + 2 * j4;
                float4 p0 = rv[0];
                float4 p1 = rv[1];
                float left = __shfl_up_sync(0xFFFFFFFFu, p1.w, 1);
                if ((j4 & 31) == 0)
                    left = (j4 == 0) ? 0.f : row[8 * j4 - 1];
                acc0 += wr * hfilt(left, p0.x, p0.y);
                acc1 += wr * hfilt(p0.y, p0.z, p0.w);
                acc2 += wr * hfilt(p0.w, p1.x, p1.y);
                acc3 += wr * hfilt(p1.y, p1.z, p1.w);
            }
            *reinterpret_cast<float4*>(op + (size_t)i * W0C + 4 * j4) =
                make_float4(acc0, acc1, acc2, acc3);
        }
    }

    // ---- Phase A2: copy rows 0..255, float4 cols 64..127 ----
    {
        const int j4 = 64 + (tid & 63);
        const int rg = tid >> 6;                 // 0..15
        #pragma unroll
        for (int it = 0; it < 16; it += 4) {
            float4 v[4];
            #pragma unroll
            for (int q = 0; q < 4; q++)
                v[q] = *(reinterpret_cast<const float4*>(
                             xp + (size_t)(rg * 16 + it + q) * W0C) + j4);
            #pragma unroll
            for (int q = 0; q < 4; q++)
                __stcs(reinterpret_cast<float4*>(
                           op + (size_t)(rg * 16 + it + q) * W0C) + j4, v[q]);
        }
    }

    // ---- Phase A3: copy rows 256..511, full width ----
    {
        const int j4 = tid & 127;
        const int rg = tid >> 7;                 // 0..7
        #pragma unroll
        for (int k = 0; k < 32; k += 4) {
            float4 v[4];
            #pragma unroll
            for (int q = 0; q < 4; q++)
                v[q] = *(reinterpret_cast<const float4*>(
                             xp + (size_t)(256 + rg * 32 + k + q) * W0C) + j4);
            #pragma unroll
            for (int q = 0; q < 4; q++)
                __stcs(reinterpret_cast<float4*>(
                           op + (size_t)(256 + rg * 32 + k + q) * W0C) + j4, v[q]);
        }
    }

    __syncthreads();   // CTA-scope: phase-A global writes visible below

    // ---- Phase B: level-1 conv from out[0:256]^2 (L2-hot) -> smem ----
    {
        const int lane = tid & 31;
        const int wy   = tid >> 5;               // 0..31
        #pragma unroll
        for (int it = 0; it < 4; it++) {
            const int i  = wy * 4 + it;          // 0..127
            const int r0 = 2 * i - 1;
            float acc0 = 0.f, acc1 = 0.f, acc2 = 0.f, acc3 = 0.f;
            #pragma unroll
            for (int a = 0; a < 3; a++) {
                const int r = r0 + a;            // <= 255
                if (r < 0) continue;             // warp-uniform
                const float wr = (a == 1) ? 0.5f : 0.25f;
                const float* row = op + (size_t)r * W0C;
                const float4* rv = reinterpret_cast<const float4*>(row) + 2 * lane;
                float4 p0 = rv[0];
                float4 p1 = rv[1];
                float left = __shfl_up_sync(0xFFFFFFFFu, p1.w, 1);
                if (lane == 0) left = 0.f;
                acc0 += wr * hfilt(left, p0.x, p0.y);
                acc1 += wr * hfilt(p0.y, p0.z, p0.w);
                acc2 += wr * hfilt(p0.w, p1.x, p1.y);
                acc3 += wr * hfilt(p1.y, p1.z, p1.w);
            }
            *reinterpret_cast<float4*>(&l1[i * L1_STRIDE + 4 * lane]) =
                make_float4(acc0, acc1, acc2, acc3);
        }
    }
    __syncthreads();

    // ---- Phase C: level-2 conv (inner 64^2) + copy -> out[0:128]^2 ----
    {
        const int lane = tid & 31;
        const int wy   = tid >> 5;
        #pragma unroll
        for (int it = 0; it < 4; it++) {
            const int i = wy * 4 + it;           // 0..127
            float4 val;
            if (i < 64 && lane < 16) {
                const int r0 = 2 * i - 1;
                float acc0 = 0.f, acc1 = 0.f, acc2 = 0.f, acc3 = 0.f;
                #pragma unroll
                for (int a = 0; a < 3; a++) {
                    const int r = r0 + a;        // <= 127
                    if (r < 0) continue;
                    const float wr = (a == 1) ? 0.5f : 0.25f;
                    const float* row = &l1[r * L1_STRIDE];
                    float4 p0 = *reinterpret_cast<const float4*>(row + 8 * lane);
                    float4 p1 = *reinterpret_cast<const float4*>(row + 8 * lane + 4);
                    float left = __shfl_up_sync(0x0000FFFFu, p1.w, 1);
                    if (lane == 0) left = 0.f;
                    acc0 += wr * hfilt(left, p0.x, p0.y);
                    acc1 += wr * hfilt(p0.y, p0.z, p0.w);
                    acc2 += wr * hfilt(p0.w, p1.x, p1.y);
                    acc3 += wr * hfilt(p1.y, p1.z, p1.w);
                }
                val = make_float4(acc0, acc1, acc2, acc3);
            } else {
                val = *reinterpret_cast<const float4*>(&l1[i * L1_STRIDE + 4 * lane]);
            }
            *reinterpret_cast<float4*>(op + (size_t)i * W0C + 4 * lane) = val;
        }
    }
}

extern "C" void kernel_launch(void* const* d_in, const int* in_sizes, int n_in,
                              void* d_out, int out_size)
{
    (void)in_sizes; (void)n_in; (void)out_size;
    const float* x = (const float*)d_in[0];
    float* out = (float*)d_out;

    static bool attr_set = false;
    if (!attr_set) {
        cudaFuncSetAttribute(wavelet_all,
                             cudaFuncAttributeMaxDynamicSharedMemorySize,
                             SMEM_BYTES);
        attr_set = true;
    }

    wavelet_all<<<dim3(BC_TOTAL), dim3(1024), SMEM_BYTES>>>(x, out);
}

// round 7
// speedup vs baseline: 1.2424x; 1.2424x over previous
#include <cuda_runtime.h>
#include <cuda_bf16.h>

// WaveletTransform: 3-level low-pass pyramid on x[8,32,512,512] fp32.
// out = x, except per-channel:
//   out[0:256,0:256] = down2x(conv3x3(x[0:512,0:512]))        (level 0)
//   out[0:128,0:128] = down2x(conv3x3(level0 result[0:256]^2)) (level 1)
//   out[0: 64,0: 64] = down2x(conv3x3(level1 result[0:128]^2)) (level 2)
// conv = outer([.25,.5,.25],[.25,.5,.25]), zero-padded 'same', even-index
// downsample (center 2i,2j -> taps 2i-1..2i+1).
//
// R4 structure (best): K1 fused copy+level0, K23 smem-fused levels 1+2.
// R7: K23 block 1024->512 with launch_bounds(512,3): 3 CTAs/SM fit by smem
//     AND threads -> all 256 CTAs resident in ONE wave (was 148+108 = two
//     serial latency-bound waves). R5 (stream overlap) and R6 (mega-kernel)
//     both regressed and are reverted.

#define BC_TOTAL (8 * 32)
#define H0 512
#define W0C 512

#define L1_STRIDE 132                       // 128 + 4 floats pad
#define K23_SMEM (128 * L1_STRIDE * 4)      // 67584 bytes

__device__ __forceinline__ float hfilt(float a, float b, float c) {
    return 0.25f * a + 0.5f * b + 0.25f * c;
}

// ---------------------------------------------------------------------------
// K1: fused identity copy + level-0 conv-down into top-left 256^2.
// grid (1,64,256), block 256. sub = tid>>7 selects a 4-row group; each thread
// owns column group j4 (float4) across 4 consecutive rows.  (unchanged, R3)
// ---------------------------------------------------------------------------
__global__ void __launch_bounds__(256) k1_copy_down0(
    const float* __restrict__ x, float* __restrict__ out)
{
    const int j4   = threadIdx.x & 127;          // 0..127 (col/4)
    const int sub  = threadIdx.x >> 7;           // 0..1
    const int base = blockIdx.y * 8 + sub * 4;   // first of 4 rows
    const int bc   = blockIdx.z;

    const float* xp = x   + (size_t)bc * H0 * W0C;
    float*       op = out + (size_t)bc * H0 * W0C;

    if (base < 256 && j4 < 64) {
        #pragma unroll
        for (int it = 0; it < 4; it++) {
            const int i  = base + it;
            const int r0 = 2 * i - 1;            // -1 only when i==0
            float acc0 = 0.f, acc1 = 0.f, acc2 = 0.f, acc3 = 0.f;
            #pragma unroll
            for (int a = 0; a < 3; a++) {
                const int r = r0 + a;            // <= 511
                if (r < 0) continue;             // warp-uniform
                const float wr = (a == 1) ? 0.5f : 0.25f;
                const float* row = xp + (size_t)r * W0C;
                const float4* rv = reinterpret_cast<const float4*>(row) + 2 * j4;
                float4 p0 = rv[0];
                float4 p1 = rv[1];
                float left = __shfl_up_sync(0xFFFFFFFFu, p1.w, 1);
                if ((j4 & 31) == 0)
                    left = (j4 == 0) ? 0.f : row[8 * j4 - 1];
                acc0 += wr * hfilt(left, p0.x, p0.y);
                acc1 += wr * hfilt(p0.y, p0.z, p0.w);
                acc2 += wr * hfilt(p0.w, p1.x, p1.y);
                acc3 += wr * hfilt(p1.y, p1.z, p1.w);
            }
            *reinterpret_cast<float4*>(op + (size_t)i * W0C + 4 * j4) =
                make_float4(acc0, acc1, acc2, acc3);
        }
    } else {
        float4 v[4];
        #pragma unroll
        for (int it = 0; it < 4; it++)
            v[it] = *(reinterpret_cast<const float4*>(
                          xp + (size_t)(base + it) * W0C) + j4);
        #pragma unroll
        for (int it = 0; it < 4; it++)
            __stcs(reinterpret_cast<float4*>(
                       op + (size_t)(base + it) * W0C) + j4, v[it]);
    }
}

// ---------------------------------------------------------------------------
// K23: fused levels 1+2. One CTA per channel, 512 threads (16 warps),
// level-1 in smem. launch_bounds(512,3) -> 3 CTAs/SM -> 256 CTAs in 1 wave.
// Phase 1: level-1 conv from out[0:256]^2 (stride 512) -> smem [128][132];
//          each warp owns 8 rows (wy*8..wy*8+7), lane = float4 col.
// Phase 2: out[0:128]^2 <- inner 64^2 conv of smem, remainder smem copy.
// ---------------------------------------------------------------------------
__global__ void __launch_bounds__(512, 3) k23_fused(float* __restrict__ out)
{
    extern __shared__ float l1[];               // [128][L1_STRIDE]
    const int lane = threadIdx.x & 31;
    const int wy   = threadIdx.x >> 5;          // 0..15
    const int bc   = blockIdx.x;

    float* op = out + (size_t)bc * H0 * W0C;

    // Phase 1: level-1 conv (reads level-0 result written by K1)
    #pragma unroll 2
    for (int it = 0; it < 8; it++) {
        const int i  = wy * 8 + it;             // 0..127
        const int r0 = 2 * i - 1;
        float acc0 = 0.f, acc1 = 0.f, acc2 = 0.f, acc3 = 0.f;
        #pragma unroll
        for (int a = 0; a < 3; a++) {
            const int r = r0 + a;               // <= 255
            if (r < 0) continue;                // warp-uniform
            const float wr = (a == 1) ? 0.5f : 0.25f;
            const float* row = op + (size_t)r * W0C;
            const float4* rv = reinterpret_cast<const float4*>(row) + 2 * lane;
            float4 p0 = rv[0];
            float4 p1 = rv[1];
            float left = __shfl_up_sync(0xFFFFFFFFu, p1.w, 1);
            if (lane == 0) left = 0.f;
            acc0 += wr * hfilt(left, p0.x, p0.y);
            acc1 += wr * hfilt(p0.y, p0.z, p0.w);
            acc2 += wr * hfilt(p0.w, p1.x, p1.y);
            acc3 += wr * hfilt(p1.y, p1.z, p1.w);
        }
        *reinterpret_cast<float4*>(&l1[i * L1_STRIDE + 4 * lane]) =
            make_float4(acc0, acc1, acc2, acc3);
    }
    __syncthreads();

    // Phase 2: level-2 conv (inner 64^2) + copy, write out[0:128]^2
    #pragma unroll 2
    for (int it = 0; it < 8; it++) {
        const int i = wy * 8 + it;              // 0..127
        float4 val;
        if (i < 64 && lane < 16) {
            const int r0 = 2 * i - 1;
            float acc0 = 0.f, acc1 = 0.f, acc2 = 0.f, acc3 = 0.f;
            #pragma unroll
            for (int a = 0; a < 3; a++) {
                const int r = r0 + a;           // <= 127
                if (r < 0) continue;
                const float wr = (a == 1) ? 0.5f : 0.25f;
                const float* row = &l1[r * L1_STRIDE];
                float4 p0 = *reinterpret_cast<const float4*>(row + 8 * lane);
                float4 p1 = *reinterpret_cast<const float4*>(row + 8 * lane + 4);
                float left = __shfl_up_sync(0x0000FFFFu, p1.w, 1);
                if (lane == 0) left = 0.f;
                acc0 += wr * hfilt(left, p0.x, p0.y);
                acc1 += wr * hfilt(p0.y, p0.z, p0.w);
                acc2 += wr * hfilt(p0.w, p1.x, p1.y);
                acc3 += wr * hfilt(p1.y, p1.z, p1.w);
            }
            val = make_float4(acc0, acc1, acc2, acc3);
        } else {
            val = *reinterpret_cast<const float4*>(&l1[i * L1_STRIDE + 4 * lane]);
        }
        *reinterpret_cast<float4*>(op + (size_t)i * W0C + 4 * lane) = val;
    }
}

extern "C" void kernel_launch(void* const* d_in, const int* in_sizes, int n_in,
                              void* d_out, int out_size)
{
    (void)in_sizes; (void)n_in; (void)out_size;
    const float* x = (const float*)d_in[0];
    float* out = (float*)d_out;

    static bool attr_set = false;
    if (!attr_set) {
        cudaFuncSetAttribute(k23_fused,
                             cudaFuncAttributeMaxDynamicSharedMemorySize,
                             K23_SMEM);
        attr_set = true;
    }

    k1_copy_down0<<<dim3(1, 64, BC_TOTAL), dim3(256)>>>(x, out);
    k23_fused    <<<dim3(BC_TOTAL), dim3(512), K23_SMEM>>>(out);
}

// round 8
// speedup vs baseline: 1.2751x; 1.0263x over previous
#include <cuda_runtime.h>
#include <cuda_bf16.h>

// WaveletTransform: 3-level low-pass pyramid on x[8,32,512,512] fp32.
// out = x, except per-channel:
//   out[0:256,0:256] = down2x(conv3x3(x[0:512,0:512]))        (level 0)
//   out[0:128,0:128] = down2x(conv3x3(level0 result[0:256]^2)) (level 1)
//   out[0: 64,0: 64] = down2x(conv3x3(level1 result[0:128]^2)) (level 2)
// conv = outer([.25,.5,.25],[.25,.5,.25]), zero-padded 'same', even-index
// downsample (center 2i,2j -> taps 2i-1..2i+1).
//
// R4 structure: K1 fused copy+level0; K23 smem-fused levels 1+2 (1024 thr).
// R8: K23 phase 1 rewritten as separable conv with a rolling 3-row load
//     pipeline (MLP~6, halved FMAs); copy-region results stored to gmem
//     directly in phase 1; phase 2 is only the inner 64^2 conv (1 float4
//     per thread). R5/R6/R7 experiments reverted.

#define BC_TOTAL (8 * 32)
#define H0 512
#define W0C 512

#define L1_STRIDE 132                       // 128 + 4 floats pad
#define K23_SMEM (128 * L1_STRIDE * 4)      // 67584 bytes

__device__ __forceinline__ float hfilt(float a, float b, float c) {
    return 0.25f * a + 0.5f * b + 0.25f * c;
}

// ---------------------------------------------------------------------------
// K1: fused identity copy + level-0 conv-down into top-left 256^2.
// grid (1,64,256), block 256.  (unchanged since R3)
// ---------------------------------------------------------------------------
__global__ void __launch_bounds__(256) k1_copy_down0(
    const float* __restrict__ x, float* __restrict__ out)
{
    const int j4   = threadIdx.x & 127;          // 0..127 (col/4)
    const int sub  = threadIdx.x >> 7;           // 0..1
    const int base = blockIdx.y * 8 + sub * 4;   // first of 4 rows
    const int bc   = blockIdx.z;

    const float* xp = x   + (size_t)bc * H0 * W0C;
    float*       op = out + (size_t)bc * H0 * W0C;

    if (base < 256 && j4 < 64) {
        #pragma unroll
        for (int it = 0; it < 4; it++) {
            const int i  = base + it;
            const int r0 = 2 * i - 1;
            float acc0 = 0.f, acc1 = 0.f, acc2 = 0.f, acc3 = 0.f;
            #pragma unroll
            for (int a = 0; a < 3; a++) {
                const int r = r0 + a;            // <= 511
                if (r < 0) continue;             // warp-uniform
                const float wr = (a == 1) ? 0.5f : 0.25f;
                const float* row = xp + (size_t)r * W0C;
                const float4* rv = reinterpret_cast<const float4*>(row) + 2 * j4;
                float4 p0 = rv[0];
                float4 p1 = rv[1];
                float left = __shfl_up_sync(0xFFFFFFFFu, p1.w, 1);
                if ((j4 & 31) == 0)
                    left = (j4 == 0) ? 0.f : row[8 * j4 - 1];
                acc0 += wr * hfilt(left, p0.x, p0.y);
                acc1 += wr * hfilt(p0.y, p0.z, p0.w);
                acc2 += wr * hfilt(p0.w, p1.x, p1.y);
                acc3 += wr * hfilt(p1.y, p1.z, p1.w);
            }
            *reinterpret_cast<float4*>(op + (size_t)i * W0C + 4 * j4) =
                make_float4(acc0, acc1, acc2, acc3);
        }
    } else {
        float4 v[4];
        #pragma unroll
        for (int it = 0; it < 4; it++)
            v[it] = *(reinterpret_cast<const float4*>(
                          xp + (size_t)(base + it) * W0C) + j4);
        #pragma unroll
        for (int it = 0; it < 4; it++)
            __stcs(reinterpret_cast<float4*>(
                       op + (size_t)(base + it) * W0C) + j4, v[it]);
    }
}

// ---------------------------------------------------------------------------
// K23: fused levels 1+2. One CTA per channel, 1024 threads, level-1 in smem.
// Phase 1 (separable, pipelined): thread (wy,lane) produces l1 rows
//   4wy..4wy+3, float4 cols 4lane..4lane+3, from level-0 rows 8wy-1..8wy+7
//   (rolling 3-row load buffer). Values outside the inner copy boundary
//   (row>=64 or lane>=16) are also stored straight to out (final, .cs).
// Phase 2: inner 64^2 level-2 conv only — thread tid: i=tid>>4, g=tid&15,
//   one float4 output from smem.
// ---------------------------------------------------------------------------
__global__ void __launch_bounds__(1024) k23_fused(float* __restrict__ out)
{
    extern __shared__ float l1[];               // [128][L1_STRIDE]
    const int tid  = threadIdx.x;
    const int lane = tid & 31;
    const int wy   = tid >> 5;                  // 0..31
    const int bc   = blockIdx.x;

    float* op = out + (size_t)bc * H0 * W0C;

    // ---- Phase 1: level-1 separable conv, rolling 3-row pipeline ----
    {
        const int rbase = 8 * wy - 1;           // may be -1 (wy==0)
        float4 A[3], B[3];

        #pragma unroll
        for (int s = 0; s < 3; s++) {
            int r = rbase + s; r = r < 0 ? 0 : r;
            const float4* rv = reinterpret_cast<const float4*>(
                                   op + (size_t)r * W0C) + 2 * lane;
            A[s] = rv[0];
            B[s] = rv[1];
        }

        float4 acc0 = make_float4(0,0,0,0), acc1 = acc0,
               acc2 = acc0, acc3 = acc0;
        // per-s weights into (accA, accB): d = s-1
        //   s:      0     1     2     3     4     5     6     7     8
        //   accA:  a0.25 a0.5  a0.25 a1.5  a1.25 a2.5  a2.25 a3.5  a3.25
        //   accB:   -     -    a1.25  -    a2.25  -    a3.25  -     -
        const float w0 = (wy == 0) ? 0.f : 0.25f;   // row -1 zero-padded

        #pragma unroll
        for (int s = 0; s < 9; s++) {
            float4 p0 = A[s % 3];
            float4 p1 = B[s % 3];
            if (s + 3 < 9) {                    // prefetch row s+3
                int r = rbase + s + 3;          // >= 2, no clamp needed
                const float4* rv = reinterpret_cast<const float4*>(
                                       op + (size_t)r * W0C) + 2 * lane;
                A[s % 3] = rv[0];
                B[s % 3] = rv[1];
            }
            float left = __shfl_up_sync(0xFFFFFFFFu, p1.w, 1);
            if (lane == 0) left = 0.f;
            float4 h;
            h.x = hfilt(left, p0.x, p0.y);
            h.y = hfilt(p0.y, p0.z, p0.w);
            h.z = hfilt(p0.w, p1.x, p1.y);
            h.w = hfilt(p1.y, p1.z, p1.w);

            float wa = 0.f; int ka = 0;
            float wb = 0.f; int kb = 0;
            switch (s) {
                case 0: wa = w0;    ka = 0; break;
                case 1: wa = 0.5f;  ka = 0; break;
                case 2: wa = 0.25f; ka = 0; wb = 0.25f; kb = 1; break;
                case 3: wa = 0.5f;  ka = 1; break;
                case 4: wa = 0.25f; ka = 1; wb = 0.25f; kb = 2; break;
                case 5: wa = 0.5f;  ka = 2; break;
                case 6: wa = 0.25f; ka = 2; wb = 0.25f; kb = 3; break;
                case 7: wa = 0.5f;  ka = 3; break;
                case 8: wa = 0.25f; ka = 3; break;
            }
            float4* accA = (ka == 0) ? &acc0 : (ka == 1) ? &acc1
                          : (ka == 2) ? &acc2 : &acc3;
            accA->x += wa * h.x; accA->y += wa * h.y;
            accA->z += wa * h.z; accA->w += wa * h.w;
            if (wb != 0.f) {
                float4* accB = (kb == 1) ? &acc1 : (kb == 2) ? &acc2 : &acc3;
                accB->x += wb * h.x; accB->y += wb * h.y;
                accB->z += wb * h.z; accB->w += wb * h.w;
            }
        }

        // store the 4 l1 rows: smem always; gmem directly where final copy
        #pragma unroll
        for (int k = 0; k < 4; k++) {
            const int i = 4 * wy + k;
            float4 v = (k == 0) ? acc0 : (k == 1) ? acc1
                       : (k == 2) ? acc2 : acc3;
            *reinterpret_cast<float4*>(&l1[i * L1_STRIDE + 4 * lane]) = v;
            if (i >= 64 || lane >= 16)
                __stcs(reinterpret_cast<float4*>(
                           op + (size_t)i * W0C + 4 * lane), v);
        }
    }
    __syncthreads();

    // ---- Phase 2: inner 64^2 level-2 conv from smem ----
    {
        const int i = tid >> 4;                 // 0..63 output row
        const int g = tid & 15;                 // float4 col group 0..15
        const int r0 = 2 * i - 1;
        float acc0 = 0.f, acc1 = 0.f, acc2 = 0.f, acc3 = 0.f;
        #pragma unroll
        for (int a = 0; a < 3; a++) {
            const int r = r0 + a;               // <= 127
            if (r < 0) continue;                // only i==0 threads skip
            const float wr = (a == 1) ? 0.5f : 0.25f;
            const float* row = &l1[r * L1_STRIDE];
            float4 p0 = *reinterpret_cast<const float4*>(row + 8 * g);
            float4 p1 = *reinterpret_cast<const float4*>(row + 8 * g + 4);
            float left = __shfl_up_sync(0xFFFFFFFFu, p1.w, 1);
            if (g == 0) left = 0.f;             // covers lanes 0 and 16
            acc0 += wr * hfilt(left, p0.x, p0.y);
            acc1 += wr * hfilt(p0.y, p0.z, p0.w);
            acc2 += wr * hfilt(p0.w, p1.x, p1.y);
            acc3 += wr * hfilt(p1.y, p1.z, p1.w);
        }
        *reinterpret_cast<float4*>(op + (size_t)i * W0C + 4 * g) =
            make_float4(acc0, acc1, acc2, acc3);
    }
}

extern "C" void kernel_launch(void* const* d_in, const int* in_sizes, int n_in,
                              void* d_out, int out_size)
{
    (void)in_sizes; (void)n_in; (void)out_size;
    const float* x = (const float*)d_in[0];
    float* out = (float*)d_out;

    static bool attr_set = false;
    if (!attr_set) {
        cudaFuncSetAttribute(k23_fused,
                             cudaFuncAttributeMaxDynamicSharedMemorySize,
                             K23_SMEM);
        attr_set = true;
    }

    k1_copy_down0<<<dim3(1, 64, BC_TOTAL), dim3(256)>>>(x, out);
    k23_fused    <<<dim3(BC_TOTAL), dim3(1024), K23_SMEM>>>(out);
}